// round 17
// baseline (speedup 1.0000x reference)
#include <cuda_runtime.h>
#include <math.h>

#define NQ 10
#define DIM 1024
#define NPAIR 45
#define NG 55
#define TT 128
#define FS 133          // padded feat row stride
#define NTH 256
#define NL 3
#define NA 3
#define PI_F 3.14159265358979323846f

typedef unsigned long long u64;

// Upper-triangle (i<j) pair indices, row-major: 45 pairs.
__constant__ int c_PI[NPAIR] = {0,0,0,0,0,0,0,0,0, 1,1,1,1,1,1,1,1, 2,2,2,2,2,2,2,
                                3,3,3,3,3,3, 4,4,4,4,4, 5,5,5,5, 6,6,6, 7,7, 8};
__constant__ int c_PJ[NPAIR] = {1,2,3,4,5,6,7,8,9, 2,3,4,5,6,7,8,9, 3,4,5,6,7,8,9,
                                4,5,6,7,8,9, 5,6,7,8,9, 6,7,8,9, 7,8,9, 8,9, 9};
// Gram tasks: all (i<=j) pairs incl diagonal, row-major: 55.
__constant__ int c_TI[NG] = {0,0,0,0,0,0,0,0,0,0, 1,1,1,1,1,1,1,1,1, 2,2,2,2,2,2,2,2,
                             3,3,3,3,3,3,3, 4,4,4,4,4,4, 5,5,5,5,5, 6,6,6,6, 7,7,7, 8,8, 9};
__constant__ int c_TJ[NG] = {0,1,2,3,4,5,6,7,8,9, 1,2,3,4,5,6,7,8,9, 2,3,4,5,6,7,8,9,
                             3,4,5,6,7,8,9, 4,5,6,7,8,9, 5,6,7,8,9, 6,7,8,9, 7,8,9, 8,9, 9};
__constant__ int c_OFF[NQ] = {0,10,19,27,34,40,45,49,52,54};
__constant__ int c_LO[9] = {0,7,14,21,28,35,42,49,55};

__device__ __forceinline__ int idx45(int i, int j) {
    return i * 9 - ((i * (i + 1)) >> 1) + j - 1;
}

__device__ __forceinline__ float2 cxmul(float2 a, float2 b) {
    return make_float2(a.x*b.x - a.y*b.y, a.x*b.y + a.y*b.x);
}
__device__ __forceinline__ float2 cxadd(float2 a, float2 b) {
    return make_float2(a.x + b.x, a.y + b.y);
}

// ---- packed f32x2 helpers ----
__device__ __forceinline__ u64 pk(float lo, float hi) {
    u64 r; asm("mov.b64 %0, {%1, %2};" : "=l"(r) : "f"(lo), "f"(hi)); return r;
}
__device__ __forceinline__ void upk(u64 v, float& lo, float& hi) {
    asm("mov.b64 {%0, %1}, %2;" : "=f"(lo), "=f"(hi) : "l"(v));
}
__device__ __forceinline__ u64 sw2(u64 v) {
    u64 r;
    asm("{\n\t.reg .b32 l0, h0;\n\tmov.b64 {l0, h0}, %1;\n\tmov.b64 %0, {h0, l0};\n\t}"
        : "=l"(r) : "l"(v));
    return r;
}
__device__ __forceinline__ u64 fmul2(u64 a, u64 b) {
    u64 d; asm("mul.rn.f32x2 %0, %1, %2;" : "=l"(d) : "l"(a), "l"(b)); return d;
}
__device__ __forceinline__ u64 ffma2(u64 a, u64 b, u64 c) {
    u64 d; asm("fma.rn.f32x2 %0, %1, %2, %3;" : "=l"(d) : "l"(a), "l"(b), "l"(c)); return d;
}

// Horizontal SU(2) gate (butterfly within each packed pair) via lane-mixed consts.
// C: {CA=(Ux,Ux), CB=(Uz,-Uz), CC=(-Uy,Uy), CD=(-Uw,-Uw), CF=(Uy,-Uy), CG=(Uw,Uw)}
__device__ __forceinline__ void hor_gate_pk(const u64* C,
                                            u64& rA, u64& iA, u64& rB, u64& iB) {
    u64 CA=C[0], CB=C[1], CC=C[2], CD=C[3], CF=C[4], CG=C[5];
    u64 rsA = sw2(rA), isA = sw2(iA), rsB = sw2(rB), isB = sw2(iB);
    u64 nrA = ffma2(CA,rA, ffma2(CB,rsA, ffma2(CC,iA, fmul2(CD,isA))));
    u64 niA = ffma2(CA,iA, ffma2(CB,isA, ffma2(CF,rA, fmul2(CG,rsA))));
    u64 nrB = ffma2(CA,rB, ffma2(CB,rsB, ffma2(CC,iB, fmul2(CD,isB))));
    u64 niB = ffma2(CA,iB, ffma2(CB,isB, ffma2(CF,rB, fmul2(CG,rsB))));
    rA=nrA; iA=niA; rB=nrB; iB=niB;
}

// SIMD SU(2) gate across the two vectors (pairs (0,2),(1,3)).
// C: {Ux2, nUy2, Uz2, nUw2, Uy2, Uw2, nUz2}
__device__ __forceinline__ void reg_gate_pk(const u64* C,
                                            u64& r0, u64& i0, u64& r1, u64& i1) {
    u64 Ux=C[0], nUy=C[1], Uz=C[2], nUw=C[3], Uy=C[4], Uw=C[5], nUz=C[6];
    u64 n0r = ffma2(Ux,r0, ffma2(nUy,i0, ffma2(Uz,r1, fmul2(nUw,i1))));
    u64 n0i = ffma2(Ux,i0, ffma2(Uy,r0, ffma2(Uz,i1, fmul2(Uw,r1))));
    u64 n1r = ffma2(nUz,r0, ffma2(nUw,i0, ffma2(Ux,r1, fmul2(Uy,i1))));
    u64 n1i = ffma2(nUz,i0, ffma2(Uw,r0, ffma2(Ux,i1, fmul2(nUy,r1))));
    r0=n0r; i0=n0i; r1=n1r; i1=n1i;
}

// Lane-shuffle SU(2) gate on lane bit k; bit-selected consts pre-baked in C.
// C: {Ux2, sy2, nsy2, sx2, Uw2, nUw2}
__device__ __forceinline__ void lane_gate_pk(const u64* C, int k,
                                             u64& rA, u64& iA, u64& rB, u64& iB) {
    u64 Ux=C[0], sy=C[1], nsy=C[2], sx=C[3], Uw=C[4], nUw=C[5];
    u64 prA = __shfl_xor_sync(0xffffffffu, rA, 1 << k);
    u64 piA = __shfl_xor_sync(0xffffffffu, iA, 1 << k);
    u64 prB = __shfl_xor_sync(0xffffffffu, rB, 1 << k);
    u64 piB = __shfl_xor_sync(0xffffffffu, iB, 1 << k);
    u64 nrA = ffma2(Ux,rA, ffma2(nsy,iA, ffma2(sx,prA, fmul2(nUw,piA))));
    u64 niA = ffma2(Ux,iA, ffma2(sy,rA, ffma2(sx,piA, fmul2(Uw,prA))));
    u64 nrB = ffma2(Ux,rB, ffma2(nsy,iB, ffma2(sx,prB, fmul2(nUw,piB))));
    u64 niB = ffma2(Ux,iB, ffma2(sy,rB, ffma2(sx,piB, fmul2(Uw,prB))));
    rA=nrA; iA=niA; rB=nrB; iB=niB;
}

// View-B map: swap amp bits [9:7] <-> slot bits [2:0].
__device__ __forceinline__ int sigma(int j) {
    return (j & 0x078) | ((j & 7) << 7) | (j >> 7);
}
__device__ __forceinline__ int ADDR(int s) { return ((s & 3) << 8) | (s >> 2); }
__device__ __forceinline__ int swz(int a) {
    return a ^ ((a >> 5) & 0xF) ^ ((a >> 1) & 8) ^ ((a >> 2) & 1);
}

__global__ __launch_bounds__(NTH, 5)
void qh_kernel(const float* __restrict__ c_kt,
               const float* __restrict__ dc_kt,
               const float* __restrict__ vqc,
               const float* __restrict__ wproj,
               const float* __restrict__ bproj,
               const float* __restrict__ lalpha,
               float* __restrict__ out)
{
    __shared__ float feat[NQ * FS];
    __shared__ float2 bufA[DIM];
    __shared__ float2 bufB[DIM];
    __shared__ int lutA[NL][32], lutB[NL][32];
    __shared__ float G[NG];
    __shared__ float Ssum[NQ];
    __shared__ float Jp[NPAIR];
    __shared__ float cth[NQ], sth[NQ], phh[NQ];
    __shared__ float thetaS[NQ], phiS[NQ];
    // packed-gate tables (broadcast constants pre-paired for f32x2)
    __shared__ __align__(16) u64 gmH[NL][2][6];     // [0]=q9 (view A), [1]=q2 (view B)
    __shared__ __align__(16) u64 gmS[NL][2][8];     // [0]=q8, [1]=q1 (7 used)
    __shared__ __align__(16) u64 gmL[NL][6][2][6];  // 0..4 = q7..q3 (k=idx), 5 = q0; [bit]
    __shared__ float wsh[NA][NQ];
    __shared__ float wred[8][4];
    __shared__ float T1mag[16], T1ph[16], T1J[16], TA1[16], TB1[16];
    __shared__ float T2mag[16], T2ph[16], T2J[16], TA2[16], TB2[16];
    __shared__ float Rrow[4][16];
    __shared__ float W1[NA][16], W2[NA][16];

    const int b    = blockIdx.x;
    const int tid  = threadIdx.x;
    const int warp = tid >> 5;
    const int lane = tid & 31;

    const float* cb = c_kt  + (size_t)b * (NQ * TT);
    const float* db = dc_kt + (size_t)b * (NQ * TT);

    // ---- phase 1: stage inputs + permutation LUTs ----
    for (int i = tid; i < NQ * TT; i += NTH) {
        int t = i / NQ, k = i - t * NQ;
        feat[k * FS + t] = fmaf(0.5f, db[i], cb[i]);
    }
    if (tid < NQ) {
        thetaS[tid] = cb[(TT - 1) * NQ + tid];
        phiS[tid]   = db[(TT - 1) * NQ + tid];
    }
    if (tid >= 224 && tid < 224 + NA * NQ) {
        int i = tid - 224;
        wsh[i / NQ][i - (i / NQ) * NQ] = wproj[i];
    }
    if (tid < 192) {
        int l = tid / 64, k = tid & 63;
        int idx = (k < 32) ? k : ((k - 32) << 5);
        const int rng = l + 1;
        #pragma unroll
        for (int q = NQ - 1; q >= 0; q--) {
            int tgt = q + rng; if (tgt >= NQ) tgt -= NQ;
            if ((idx >> (NQ - 1 - q)) & 1) idx ^= 1 << (NQ - 1 - tgt);
        }
        int p = swz(ADDR(sigma(idx)));
        if (k < 32) lutA[l][k] = p; else lutB[l][k - 32] = p;
    }
    __syncthreads();

    // ---- phase 2: Gram dots + fused row sums ----
    {
        const int lo = c_LO[warp], hi = c_LO[warp + 1];
        int cur_i = -1;
        float vi0=0.f, vi1=0.f, vi2=0.f, vi3=0.f;
        for (int tk = lo; tk < hi; tk++) {
            int i = c_TI[tk], j = c_TJ[tk];
            if (i != cur_i) {
                cur_i = i;
                const float* fi = feat + i * FS + lane;
                vi0 = fi[0]; vi1 = fi[32]; vi2 = fi[64]; vi3 = fi[96];
            }
            float s;
            if (j == i) {
                s = vi0*vi0 + vi1*vi1 + vi2*vi2 + vi3*vi3;
                float ss = vi0 + vi1 + vi2 + vi3;
                #pragma unroll
                for (int o = 16; o; o >>= 1) ss += __shfl_xor_sync(0xffffffffu, ss, o);
                if (lane == 0) Ssum[i] = ss;
            } else {
                const float* fj = feat + j * FS + lane;
                s = vi0*fj[0] + vi1*fj[32] + vi2*fj[64] + vi3*fj[96];
            }
            #pragma unroll
            for (int o = 16; o; o >>= 1) s += __shfl_xor_sync(0xffffffffu, s, o);
            if (lane == 0) G[tk] = s;
        }
    }
    __syncthreads();

    // ---- phase 3 (parallel sub-jobs) ----
    if (tid < NPAIR) {
        int i = c_PI[tid], j = c_PJ[tid];
        float Si = Ssum[i], Sj = Ssum[j];
        const float invT = 1.f / TT, invT1 = 1.f / (TT - 1);
        float vi = (G[c_OFF[i]] - Si * Si * invT) * invT1;
        float vj = (G[c_OFF[j]] - Sj * Sj * invT) * invT1;
        float si = fmaxf(sqrtf(vi), 1e-8f);
        float sj = fmaxf(sqrtf(vj), 1e-8f);
        float num = (G[c_OFF[i] + (j - i)] - Si * Sj * invT) * invT1;
        float rho = num / (si * sj);
        Jp[tid] = __tanhf(rho * __expf(lalpha[0]));
    } else if (tid >= 64 && tid < 64 + NQ) {
        int q = tid - 64;
        float sq, cq;
        __sincosf(0.5f * thetaS[q], &sq, &cq);
        cth[q] = cq; sth[q] = sq;
        phh[q] = 0.5f * phiS[q];
    } else if (tid >= 128 && tid < 128 + NL * NQ) {
        int idx = tid - 128;
        int l = idx / NQ, q = idx - l * NQ;
        float a  = vqc[idx * 3 + 0];
        float bb = vqc[idx * 3 + 1];
        float c  = vqc[idx * 3 + 2];
        float sb2, cb2; __sincosf(0.5f * bb, &sb2, &cb2);
        float apc = 0.5f * (a + c), amc = 0.5f * (a - c);
        float capc, sapc, camc, samc;
        __sincosf(apc, &sapc, &capc);
        __sincosf(amc, &samc, &camc);
        float2 u00 = make_float2( capc * cb2, -sapc * cb2);
        float2 u01 = make_float2(-camc * sb2, -samc * sb2);
        if (l != 0) {
            // Fold preceding RY(theta/2), RZ(phi/2) into this layer's rot (SU(2)).
            float thq = 0.25f * thetaS[q], phq = 0.25f * phiS[q];
            float st, ct; __sincosf(thq, &st, &ct);
            float sp, cp; __sincosf(phq, &sp, &cp);
            float2 A00 = make_float2( cp * ct, -sp * ct);
            float2 A01 = make_float2(-cp * st,  sp * st);
            float2 A10 = make_float2(-A01.x,  A01.y);
            float2 A11 = make_float2( A00.x, -A00.y);
            float2 v00 = cxadd(cxmul(u00, A00), cxmul(u01, A10));
            float2 v01 = cxadd(cxmul(u00, A01), cxmul(u01, A11));
            u00 = v00; u01 = v01;
        }
        // Expand into packed broadcast-constant tables.
        float Ux = u00.x, Uy = u00.y, Uz = u01.x, Uw = u01.y;
        if (q == 9 || q == 2) {
            u64* d = gmH[l][(q == 9) ? 0 : 1];
            d[0] = pk(Ux, Ux);   d[1] = pk(Uz, -Uz);  d[2] = pk(-Uy, Uy);
            d[3] = pk(-Uw, -Uw); d[4] = pk(Uy, -Uy);  d[5] = pk(Uw, Uw);
        } else if (q == 8 || q == 1) {
            u64* d = gmS[l][(q == 8) ? 0 : 1];
            d[0] = pk(Ux, Ux);   d[1] = pk(-Uy, -Uy); d[2] = pk(Uz, Uz);
            d[3] = pk(-Uw, -Uw); d[4] = pk(Uy, Uy);   d[5] = pk(Uw, Uw);
            d[6] = pk(-Uz, -Uz);
        } else {
            int li = (q == 0) ? 5 : (7 - q);
            #pragma unroll
            for (int bit = 0; bit < 2; bit++) {
                float sy = bit ? -Uy : Uy;
                float sx = bit ? -Uz : Uz;
                u64* d = gmL[l][li][bit];
                d[0] = pk(Ux, Ux); d[1] = pk(sy, sy);  d[2] = pk(-sy, -sy);
                d[3] = pk(sx, sx); d[4] = pk(Uw, Uw);  d[5] = pk(-Uw, -Uw);
            }
        }
    }
    __syncthreads();

    // ---- phase 3.5: nibble tables ----
    if (tid < 16) {
        int h = tid;
        float m = 1.f, p = 0.f, jj = 0.f, aa = 0.f, bv = 0.f;
        #pragma unroll
        for (int q = 0; q < 4; q++) {
            bool bit = (h >> (3 - q)) & 1;
            m *= bit ? sth[q] : cth[q];
            p += bit ? phh[q] : -phh[q];
            float ja = Jp[idx45(q, 8)], jb = Jp[idx45(q, 9)];
            aa += bit ? ja : -ja;
            bv += bit ? jb : -jb;
        }
        #pragma unroll
        for (int i = 0; i < 3; i++)
            #pragma unroll
            for (int j2 = i + 1; j2 < 4; j2++) {
                bool si = (h >> (3 - i)) & 1, sj = (h >> (3 - j2)) & 1;
                float v = Jp[idx45(i, j2)];
                jj += (si ^ sj) ? v : -v;
            }
        T1mag[h] = m; T1ph[h] = p; T1J[h] = jj; TA1[h] = aa; TB1[h] = bv;
    } else if (tid < 32) {
        int h = tid - 16;
        float m = 1.f, p = 0.f, jj = 0.f, aa = 0.f, bv = 0.f;
        #pragma unroll
        for (int q = 4; q < 8; q++) {
            bool bit = (h >> (7 - q)) & 1;
            m *= bit ? sth[q] : cth[q];
            p += bit ? phh[q] : -phh[q];
            float ja = Jp[idx45(q, 8)], jb = Jp[idx45(q, 9)];
            aa += bit ? ja : -ja;
            bv += bit ? jb : -jb;
        }
        #pragma unroll
        for (int i = 4; i < 7; i++)
            #pragma unroll
            for (int j2 = i + 1; j2 < 8; j2++) {
                bool si = (h >> (7 - i)) & 1, sj = (h >> (7 - j2)) & 1;
                float v = Jp[idx45(i, j2)];
                jj += (si ^ sj) ? v : -v;
            }
        T2mag[h] = m; T2ph[h] = p; T2J[h] = jj; TA2[h] = aa; TB2[h] = bv;
    } else if (tid < 96) {
        int e = tid - 32;
        int i = e >> 4, h2 = e & 15;
        float r = 0.f;
        #pragma unroll
        for (int j2 = 4; j2 < 8; j2++) {
            bool bit = (h2 >> (7 - j2)) & 1;
            float v = Jp[idx45(i, j2)];
            r += bit ? v : -v;
        }
        Rrow[i][h2] = r;
    } else if (tid < 192) {
        int e = tid - 96;
        int half = e / 48;
        int rem = e - half * 48;
        int a = rem >> 4, h = rem & 15;
        float g = 0.f;
        #pragma unroll
        for (int k = 0; k < 4; k++) {
            int q = half * 4 + k;
            bool bit = (h >> (3 - k)) & 1;
            float w = wsh[a][q];
            g += bit ? -w : w;
        }
        if (half == 0) W1[a][h] = g; else W2[a][h] = g;
    }
    __syncthreads();

    // ===================== state (packed f32x2) =====================
    u64 rA, iA, rB, iB;   // (a0,a1) and (a2,a3); r bit1=q8, bit0=q9
    {
        const int h1 = tid >> 4, h2 = tid & 15;
        float magHi = T1mag[h1] * T2mag[h2];
        float phHi  = T1ph[h1] + T2ph[h2];
        float base  = T1J[h1] + T2J[h2];
        #pragma unroll
        for (int i = 0; i < 4; i++) {
            bool ti = (h1 >> (3 - i)) & 1;
            float rv = Rrow[i][h2];
            base += ti ? -rv : rv;
        }
        float A  = TA1[h1] + TA2[h2];
        float Bv = TB1[h1] + TB2[h2];
        float C = Jp[44];
        float c8 = cth[8], s8 = sth[8], c9 = cth[9], s9 = sth[9];
        float p8 = phh[8], p9 = phh[9];
        float sR0[4], sI0[4];
        #pragma unroll
        for (int r = 0; r < 4; r++) {
            bool b8 = (r >> 1) & 1, b9 = r & 1;
            float mag = magHi * (b8 ? s8 : c8) * (b9 ? s9 : c9);
            float ph  = phHi + (b8 ? p8 : -p8) + (b9 ? p9 : -p9);
            float aJ  = base + (b8 ? -A : A) + (b9 ? -Bv : Bv) + ((b8 ^ b9) ? C : -C);
            ph = fmaf(0.5f * PI_F, aJ, ph);
            float sp, cp; __sincosf(ph, &sp, &cp);
            sR0[r] = mag * cp; sI0[r] = mag * sp;
        }
        rA = pk(sR0[0], sR0[1]); iA = pk(sI0[0], sI0[1]);
        rB = pk(sR0[2], sR0[3]); iB = pk(sI0[2], sI0[3]);
    }

    const int ftid = swz(tid);
    int pbase = (((tid >> 5) & 3) << 8) | (tid & 0x1E) | ((tid & 1) << 7) | (tid >> 7);
    const int fpb = swz(pbase);
    const int cstS[4] = {0x000, 0x108, 0x200, 0x308};
    const int cstG[4] = {0x00, 0x21, 0x42, 0x63};
    const int laIdxBase = (tid & 7) << 2;
    const int lbIdx = tid >> 3;

    #pragma unroll
    for (int l = 0; l < NL; l++) {
        // view A: q9 (horizontal), q8 (SIMD), q7..q3 (lane bits 0..4)
        hor_gate_pk(gmH[l][0], rA, iA, rB, iB);
        reg_gate_pk(gmS[l][0], rA, iA, rB, iB);
        #pragma unroll
        for (int k = 0; k < 5; k++)
            lane_gate_pk(gmL[l][k][(lane >> k) & 1], k, rA, iA, rB, iB);

        // exchange to view B
        {
            float r0,r1,r2,r3, i0,i1,i2,i3;
            upk(rA, r0, r1); upk(iA, i0, i1);
            upk(rB, r2, r3); upk(iB, i2, i3);
            bufA[ftid ^ cstS[0]] = make_float2(r0, i0);
            bufA[ftid ^ cstS[1]] = make_float2(r1, i1);
            bufA[ftid ^ cstS[2]] = make_float2(r2, i2);
            bufA[ftid ^ cstS[3]] = make_float2(r3, i3);
        }
        __syncthreads();
        {
            float2 v0 = bufA[fpb ^ cstG[0]];
            float2 v1 = bufA[fpb ^ cstG[1]];
            float2 v2 = bufA[fpb ^ cstG[2]];
            float2 v3 = bufA[fpb ^ cstG[3]];
            rA = pk(v0.x, v1.x); iA = pk(v0.y, v1.y);
            rB = pk(v2.x, v3.x); iB = pk(v2.y, v3.y);
        }

        // view B: q2 (horizontal), q1 (SIMD), q0 (lane bit 0)
        hor_gate_pk(gmH[l][1], rA, iA, rB, iB);
        reg_gate_pk(gmS[l][1], rA, iA, rB, iB);
        lane_gate_pk(gmL[l][5][lane & 1], 0, rA, iA, rB, iB);

        // exchange back + composed-CNOT permutation via linear LUT
        {
            float r0,r1,r2,r3, i0,i1,i2,i3;
            upk(rA, r0, r1); upk(iA, i0, i1);
            upk(rB, r2, r3); upk(iB, i2, i3);
            bufB[ftid ^ cstS[0]] = make_float2(r0, i0);
            bufB[ftid ^ cstS[1]] = make_float2(r1, i1);
            bufB[ftid ^ cstS[2]] = make_float2(r2, i2);
            bufB[ftid ^ cstS[3]] = make_float2(r3, i3);
        }
        __syncthreads();
        {
            int mb = lutB[l][lbIdx];
            float2 v0 = bufB[mb ^ lutA[l][laIdxBase | 0]];
            float2 v1 = bufB[mb ^ lutA[l][laIdxBase | 1]];
            float2 v2 = bufB[mb ^ lutA[l][laIdxBase | 2]];
            float2 v3 = bufB[mb ^ lutA[l][laIdxBase | 3]];
            rA = pk(v0.x, v1.x); iA = pk(v0.y, v1.y);
            rB = pk(v2.x, v3.x); iB = pk(v2.y, v3.y);
        }
    }

    // ---- epilogue ----
    {
        float eR[4], eI[4];
        upk(rA, eR[0], eR[1]); upk(iA, eI[0], eI[1]);
        upk(rB, eR[2], eR[3]); upk(iB, eI[2], eI[3]);
        const int h1 = tid >> 4, h2 = tid & 15;
        float g0Hi = W1[0][h1] + W2[0][h2];
        float g1Hi = W1[1][h1] + W2[1][h2];
        float g2Hi = W1[2][h1] + W2[2][h2];
        float w08 = wsh[0][8], w09 = wsh[0][9];
        float w18 = wsh[1][8], w19 = wsh[1][9];
        float w28 = wsh[2][8], w29 = wsh[2][9];
        float acc0 = 0.f, acc1 = 0.f, acc2 = 0.f;
        #pragma unroll
        for (int r = 0; r < 4; r++) {
            bool b8 = (r >> 1) & 1, b9 = r & 1;
            float pr = eR[r]*eR[r] + eI[r]*eI[r];
            acc0 = fmaf(pr, g0Hi + (b8 ? -w08 : w08) + (b9 ? -w09 : w09), acc0);
            acc1 = fmaf(pr, g1Hi + (b8 ? -w18 : w18) + (b9 ? -w19 : w19), acc1);
            acc2 = fmaf(pr, g2Hi + (b8 ? -w28 : w28) + (b9 ? -w29 : w29), acc2);
        }
        #pragma unroll
        for (int o = 16; o; o >>= 1) {
            acc0 += __shfl_xor_sync(0xffffffffu, acc0, o);
            acc1 += __shfl_xor_sync(0xffffffffu, acc1, o);
            acc2 += __shfl_xor_sync(0xffffffffu, acc2, o);
        }
        if (lane == 0) {
            wred[warp][0] = acc0; wred[warp][1] = acc1; wred[warp][2] = acc2;
        }
    }
    __syncthreads();
    if (tid < NA) {
        float s = bproj[tid];
        #pragma unroll
        for (int w = 0; w < 8; w++) s += wred[w][tid];
        out[b * NA + tid] = s;
    }
}

extern "C" void kernel_launch(void* const* d_in, const int* in_sizes, int n_in,
                              void* d_out, int out_size) {
    const float* c_kt   = (const float*)d_in[0];
    const float* dc_kt  = (const float*)d_in[1];
    const float* vqc    = (const float*)d_in[2];
    const float* wproj  = (const float*)d_in[3];
    const float* bproj  = (const float*)d_in[4];
    const float* lalpha = (const float*)d_in[5];
    int B = in_sizes[0] / (NQ * TT);
    qh_kernel<<<B, NTH>>>(c_kt, dc_kt, vqc, wproj, bproj, lalpha, (float*)d_out);
}